// round 13
// baseline (speedup 1.0000x reference)
#include <cuda_runtime.h>
#include <cuda_bf16.h>
#include <cuda_fp16.h>
#include <cstdint>

#define N_USERS 40000
#define N_ITEMS 60000
#define N_NODES 100000
#define N_EDGES 1280000
#define EMB 64
#define NEG_SLOPE 0.2f

#define SCAN_BLK 1024
#define NSCAN_BLOCKS ((N_NODES + SCAN_BLK - 1) / SCAN_BLK)   // 98

// ---------------- scratch ----------------
__device__ float  g_ea[N_NODES * EMB];
__device__ float  g_eb[N_NODES * EMB];
__device__ __half g_eha[N_NODES * EMB];   // fp16 gather mirror (ping)
__device__ __half g_ehb[N_NODES * EMB];   // fp16 gather mirror (pong)
__device__ int    g_deg[N_NODES];
__device__ int    g_off[N_NODES];
__device__ int    g_head[N_NODES];
__device__ int    g_bsum[NSCAN_BLOCKS];
__device__ int2   g_csr_cv[N_EDGES];

// smem layout (bytes). K-stride = 136 bf16 = 272 B (68 words -> 4-bank shift/row)
#define KS 272
#define BB_OFF   0
#define SROW_OFF 256                         // 128 x 2 floats = 1024 B
#define AHI_OFF  1280
#define ALO_OFF  (AHI_OFF + 128 * KS)        // 36096
#define BHI_OFF  (ALO_OFF + 128 * KS)        // 70912
#define BLO_OFF  (BHI_OFF + 64 * KS)         // 88320
#define TC_SMEM  (BLO_OFF + 64 * KS)         // 105728

// ---------------------------------------------------------------------------
// helpers
// ---------------------------------------------------------------------------
__device__ __forceinline__ uint32_t packbf(float lo, float hi) {
    uint32_t r;
    asm("cvt.rn.bf16x2.f32 %0, %1, %2;" : "=r"(r) : "f"(hi), "f"(lo));
    return r;
}
__device__ __forceinline__ float bfhi(float x) {
    __nv_bfloat16 h = __float2bfloat16(x);
    return __bfloat162float(h);
}
__device__ __forceinline__ void mma_bf16(float* c, uint32_t a0, uint32_t a1,
                                         uint32_t a2, uint32_t a3,
                                         uint32_t b0, uint32_t b1) {
    asm volatile(
        "mma.sync.aligned.m16n8k16.row.col.f32.bf16.bf16.f32 "
        "{%0,%1,%2,%3}, {%4,%5,%6,%7}, {%8,%9}, {%0,%1,%2,%3};"
        : "+f"(c[0]), "+f"(c[1]), "+f"(c[2]), "+f"(c[3])
        : "r"(a0), "r"(a1), "r"(a2), "r"(a3), "r"(b0), "r"(b1));
}
// 4 halves (as uint2) -> float4
__device__ __forceinline__ float4 h4_to_f4(uint2 q) {
    float2 p0 = __half22float2(*(const __half2*)&q.x);
    float2 p1 = __half22float2(*(const __half2*)&q.y);
    return make_float4(p0.x, p0.y, p1.x, p1.y);
}

// ---------------------------------------------------------------------------
// init / CSR build (prelude; also fills the fp16 mirror)
// ---------------------------------------------------------------------------
__global__ void k_init(const float* __restrict__ ue, const float* __restrict__ ie,
                       float* __restrict__ out) {
    int i = blockIdx.x * blockDim.x + threadIdx.x;
    const int total4 = N_NODES * EMB / 4;
    if (i < N_NODES) g_deg[i] = 0;
    if (i >= total4) return;
    const int user4 = N_USERS * EMB / 4;
    float4 v;
    if (i < user4) v = ((const float4*)ue)[i];
    else           v = ((const float4*)ie)[i - user4];
    ((float4*)g_ea)[i] = v;
    ((float4*)out)[i] = v;
    __half2 h0 = __floats2half2_rn(v.x, v.y);
    __half2 h1 = __floats2half2_rn(v.z, v.w);
    ((uint2*)g_eha)[i] = make_uint2(*(uint32_t*)&h0, *(uint32_t*)&h1);
}

__global__ void k_hist(const int* __restrict__ erow) {
    int i = blockIdx.x * blockDim.x + threadIdx.x;
    if (i < N_EDGES) atomicAdd(&g_deg[erow[i]], 1);
}

__global__ void __launch_bounds__(SCAN_BLK) k_scanA() {
    __shared__ int s[SCAN_BLK];
    int i = blockIdx.x * SCAN_BLK + threadIdx.x;
    int v = (i < N_NODES) ? g_deg[i] : 0;
    s[threadIdx.x] = v;
    __syncthreads();
    int inc = v;
    #pragma unroll
    for (int d = 1; d < SCAN_BLK; d <<= 1) {
        int t = (threadIdx.x >= d) ? s[threadIdx.x - d] : 0;
        __syncthreads();
        inc += t;
        s[threadIdx.x] = inc;
        __syncthreads();
    }
    if (i < N_NODES) g_off[i] = inc - v;
    if (threadIdx.x == SCAN_BLK - 1) g_bsum[blockIdx.x] = inc;
}

__global__ void __launch_bounds__(256) k_scanC() {
    __shared__ int s_carry;
    int sb = blockIdx.x >> 2;
    if (threadIdx.x < 32) {
        int sum = 0;
        for (int i = threadIdx.x; i < sb; i += 32) sum += g_bsum[i];
        #pragma unroll
        for (int d = 16; d; d >>= 1) sum += __shfl_xor_sync(0xffffffffu, sum, d);
        if (threadIdx.x == 0) s_carry = sum;
    }
    __syncthreads();
    int i = blockIdx.x * 256 + threadIdx.x;
    if (i >= N_NODES) return;
    int o = g_off[i] + s_carry;
    g_off[i] = o;
    g_head[i] = o;
}

__global__ void k_scatter(const int* __restrict__ erow, const int* __restrict__ ecol,
                          const float* __restrict__ eval) {
    int i = blockIdx.x * blockDim.x + threadIdx.x;
    if (i >= N_EDGES) return;
    int r = erow[i];
    int pos = atomicAdd(&g_head[r], 1);
    g_csr_cv[pos] = make_int2(ecol[i], __float_as_int(eval[i]));
}

// ---------------------------------------------------------------------------
// Fused layer, tensor-core GEMM, 512 threads (16 warps), 128 nodes/block.
// Gather reads the fp16 mirror (128B/row = 1 cache line per edge).
// ---------------------------------------------------------------------------
extern __shared__ char sm_tc[];

__global__ void __launch_bounds__(512, 2) k_layer_tc(
    const float* __restrict__ W1, const float* __restrict__ b1,
    const float* __restrict__ W2, const float* __restrict__ b2,
    float* __restrict__ out, float scale, int flag) {

    char* sm = sm_tc;
    const float*  esrc  = flag ? g_eb  : g_ea;
    float*        edst  = flag ? g_ea  : g_eb;
    const __half* ehsrc = flag ? g_ehb : g_eha;
    __half*       ehdst = flag ? g_eha : g_ehb;

    const int tid = threadIdx.x;
    const int w   = tid >> 5;
    const int l   = tid & 31;
    const int base = blockIdx.x * 128;

    // bias: threads 0..63
    if (tid < 64) ((float*)(sm + BB_OFF))[tid] = b1[tid] + b2[tid];

    // ---- build B tiles: Bt[n][k] = (k<64 ? W1[k][n] : W2[k-64][n]) ----
    {
        int n  = tid >> 3;        // 0..63
        int kq = tid & 7;         // 16-wide k block
        #pragma unroll
        for (int g = 0; g < 4; g++) {
            int k = kq * 16 + g * 4;
            float wv[4];
            #pragma unroll
            for (int c = 0; c < 4; c++) {
                int kk = k + c;
                wv[c] = (kk < 64) ? __ldg(W1 + kk * 64 + n)
                                  : __ldg(W2 + (kk - 64) * 64 + n);
            }
            float h0 = bfhi(wv[0]), h1 = bfhi(wv[1]), h2 = bfhi(wv[2]), h3 = bfhi(wv[3]);
            uint2 hi = make_uint2(packbf(h0, h1), packbf(h2, h3));
            uint2 lo = make_uint2(packbf(wv[0] - h0, wv[1] - h1),
                                  packbf(wv[2] - h2, wv[3] - h3));
            int off = n * KS + k * 2;
            *(uint2*)(sm + BHI_OFF + off) = hi;
            *(uint2*)(sm + BLO_OFF + off) = lo;
        }
    }

    // ---- gather (fp16 mirror) + build A tiles: 4 slices of 32 nodes ----
    const uint2* eh4 = (const uint2*)ehsrc;   // 8B = 4 halves per chunk
    #pragma unroll 1
    for (int it = 0; it < 4; it++) {
        int nd = (tid >> 4) + it * 32;     // local node 0..127
        int c  = tid & 15;                 // 4-element chunk
        int node = base + nd;
        float4 xa = make_float4(0.f, 0.f, 0.f, 0.f);
        float4 xb = make_float4(0.f, 0.f, 0.f, 0.f);
        float4 ev = make_float4(0.f, 0.f, 0.f, 0.f);
        if (node < N_NODES) {
            int start = g_off[node];
            int deg = g_deg[node];
            int j = 0;
            for (; j + 3 < deg; j += 4) {
                int2 cv0 = g_csr_cv[start + j];
                int2 cv1 = g_csr_cv[start + j + 1];
                int2 cv2 = g_csr_cv[start + j + 2];
                int2 cv3 = g_csr_cv[start + j + 3];
                float4 f0 = h4_to_f4(__ldg(eh4 + cv0.x * 16 + c));
                float4 f1 = h4_to_f4(__ldg(eh4 + cv1.x * 16 + c));
                float4 f2 = h4_to_f4(__ldg(eh4 + cv2.x * 16 + c));
                float4 f3 = h4_to_f4(__ldg(eh4 + cv3.x * 16 + c));
                float v0 = __int_as_float(cv0.y), v1 = __int_as_float(cv1.y);
                float v2 = __int_as_float(cv2.y), v3 = __int_as_float(cv3.y);
                xa.x += v0 * f0.x; xa.y += v0 * f0.y; xa.z += v0 * f0.z; xa.w += v0 * f0.w;
                xb.x += v1 * f1.x; xb.y += v1 * f1.y; xb.z += v1 * f1.z; xb.w += v1 * f1.w;
                xa.x += v2 * f2.x; xa.y += v2 * f2.y; xa.z += v2 * f2.z; xa.w += v2 * f2.w;
                xb.x += v3 * f3.x; xb.y += v3 * f3.y; xb.z += v3 * f3.z; xb.w += v3 * f3.w;
            }
            for (; j < deg; j++) {
                int2 cv0 = g_csr_cv[start + j];
                float v0 = __int_as_float(cv0.y);
                float4 f0 = h4_to_f4(__ldg(eh4 + cv0.x * 16 + c));
                xa.x += v0 * f0.x; xa.y += v0 * f0.y; xa.z += v0 * f0.z; xa.w += v0 * f0.w;
            }
            xa.x += xb.x; xa.y += xb.y; xa.z += xb.z; xa.w += xb.w;
            ev = __ldg(((const float4*)esrc) + node * 16 + c);
        }
        float4 u = make_float4(ev.x + xa.x, ev.y + xa.y, ev.z + xa.z, ev.w + xa.w);
        float4 v = make_float4(ev.x * xa.x, ev.y * xa.y, ev.z * xa.z, ev.w * xa.w);

        float uh0 = bfhi(u.x), uh1 = bfhi(u.y), uh2 = bfhi(u.z), uh3 = bfhi(u.w);
        float vh0 = bfhi(v.x), vh1 = bfhi(v.y), vh2 = bfhi(v.z), vh3 = bfhi(v.w);
        int offU = nd * KS + c * 8;          // k = 4c
        int offV = nd * KS + 128 + c * 8;    // k = 64 + 4c
        *(uint2*)(sm + AHI_OFF + offU) = make_uint2(packbf(uh0, uh1), packbf(uh2, uh3));
        *(uint2*)(sm + ALO_OFF + offU) = make_uint2(packbf(u.x - uh0, u.y - uh1),
                                                    packbf(u.z - uh2, u.w - uh3));
        *(uint2*)(sm + AHI_OFF + offV) = make_uint2(packbf(vh0, vh1), packbf(vh2, vh3));
        *(uint2*)(sm + ALO_OFF + offV) = make_uint2(packbf(v.x - vh0, v.y - vh1),
                                                    packbf(v.z - vh2, v.w - vh3));
    }
    __syncthreads();

    // ---- tensor-core GEMM ----
    const int wr = w >> 1;                 // row group 0..7
    const int wc = w & 1;                  // column half 0/1
    float acc[4][4];
    #pragma unroll
    for (int nt = 0; nt < 4; nt++)
        #pragma unroll
        for (int q = 0; q < 4; q++) acc[nt][q] = 0.f;

    const char* smAh = sm + AHI_OFF;
    const char* smAl = sm + ALO_OFF;
    const char* smBh = sm + BHI_OFF;
    const char* smBl = sm + BLO_OFF;
    const int rowA = (16 * wr + (l >> 2)) * KS;
    const int lk   = (l & 3) * 4;

    #pragma unroll
    for (int ks = 0; ks < 8; ks++) {
        int kb = ks * 32 + lk;
        uint32_t ah0 = *(const uint32_t*)(smAh + rowA + kb);
        uint32_t ah1 = *(const uint32_t*)(smAh + rowA + 8 * KS + kb);
        uint32_t ah2 = *(const uint32_t*)(smAh + rowA + kb + 16);
        uint32_t ah3 = *(const uint32_t*)(smAh + rowA + 8 * KS + kb + 16);
        uint32_t al0 = *(const uint32_t*)(smAl + rowA + kb);
        uint32_t al1 = *(const uint32_t*)(smAl + rowA + 8 * KS + kb);
        uint32_t al2 = *(const uint32_t*)(smAl + rowA + kb + 16);
        uint32_t al3 = *(const uint32_t*)(smAl + rowA + 8 * KS + kb + 16);
        #pragma unroll
        for (int nt = 0; nt < 4; nt++) {
            int rowB = (wc * 32 + nt * 8 + (l >> 2)) * KS + kb;
            uint32_t bh0 = *(const uint32_t*)(smBh + rowB);
            uint32_t bh1 = *(const uint32_t*)(smBh + rowB + 16);
            uint32_t bl0 = *(const uint32_t*)(smBl + rowB);
            uint32_t bl1 = *(const uint32_t*)(smBl + rowB + 16);
            mma_bf16(acc[nt], ah0, ah1, ah2, ah3, bh0, bh1);
            mma_bf16(acc[nt], ah0, ah1, ah2, ah3, bl0, bl1);
            mma_bf16(acc[nt], al0, al1, al2, al3, bh0, bh1);
        }
    }

    // ---- epilogue: bias + leaky, partial row sums, cross-warp combine ----
    const float* bb = (const float*)(sm + BB_OFF);
    float* srow = (float*)(sm + SROW_OFF);   // [128][2]
    float ss0 = 0.f, ss1 = 0.f;
    #pragma unroll
    for (int nt = 0; nt < 4; nt++) {
        int col0 = wc * 32 + nt * 8 + (l & 3) * 2;
        float bc0 = bb[col0], bc1 = bb[col0 + 1];
        float h;
        h = acc[nt][0] + bc0; h = (h >= 0.f) ? h : NEG_SLOPE * h; acc[nt][0] = h; ss0 += h * h;
        h = acc[nt][1] + bc1; h = (h >= 0.f) ? h : NEG_SLOPE * h; acc[nt][1] = h; ss0 += h * h;
        h = acc[nt][2] + bc0; h = (h >= 0.f) ? h : NEG_SLOPE * h; acc[nt][2] = h; ss1 += h * h;
        h = acc[nt][3] + bc1; h = (h >= 0.f) ? h : NEG_SLOPE * h; acc[nt][3] = h; ss1 += h * h;
    }
    ss0 += __shfl_xor_sync(0xffffffffu, ss0, 1);
    ss0 += __shfl_xor_sync(0xffffffffu, ss0, 2);
    ss1 += __shfl_xor_sync(0xffffffffu, ss1, 1);
    ss1 += __shfl_xor_sync(0xffffffffu, ss1, 2);

    int r0l = 16 * wr + (l >> 2);
    if ((l & 3) == 0) {
        srow[r0l * 2 + wc] = ss0;
        srow[(r0l + 8) * 2 + wc] = ss1;
    }
    __syncthreads();
    float inv0 = rsqrtf(fmaxf(srow[r0l * 2] + srow[r0l * 2 + 1], 1e-24f));
    float inv1 = rsqrtf(fmaxf(srow[(r0l + 8) * 2] + srow[(r0l + 8) * 2 + 1], 1e-24f));

    int r0 = base + r0l;
    int r1 = r0 + 8;
    if (r0 < N_NODES) {
        #pragma unroll
        for (int nt = 0; nt < 4; nt++) {
            int col0 = wc * 32 + nt * 8 + (l & 3) * 2;
            float e0 = acc[nt][0] * inv0, e1 = acc[nt][1] * inv0;
            *(float2*)(edst + r0 * 64 + col0) = make_float2(e0, e1);
            *(__half2*)(ehdst + r0 * 64 + col0) = __floats2half2_rn(e0, e1);
            float2 o = *(float2*)(out + r0 * 64 + col0);
            o.x = (o.x + e0) * scale;
            o.y = (o.y + e1) * scale;
            *(float2*)(out + r0 * 64 + col0) = o;
        }
    }
    if (r1 < N_NODES) {
        #pragma unroll
        for (int nt = 0; nt < 4; nt++) {
            int col0 = wc * 32 + nt * 8 + (l & 3) * 2;
            float e0 = acc[nt][2] * inv1, e1 = acc[nt][3] * inv1;
            *(float2*)(edst + r1 * 64 + col0) = make_float2(e0, e1);
            *(__half2*)(ehdst + r1 * 64 + col0) = __floats2half2_rn(e0, e1);
            float2 o = *(float2*)(out + r1 * 64 + col0);
            o.x = (o.x + e0) * scale;
            o.y = (o.y + e1) * scale;
            *(float2*)(out + r1 * 64 + col0) = o;
        }
    }
}

// ---------------------------------------------------------------------------
extern "C" void kernel_launch(void* const* d_in, const int* in_sizes, int n_in,
                              void* d_out, int out_size) {
    const int*   erow = (const int*)d_in[0];
    const int*   ecol = (const int*)d_in[1];
    const float* eval = (const float*)d_in[2];
    const float* ue   = (const float*)d_in[3];
    const float* ie   = (const float*)d_in[4];
    const float* W1   = (const float*)d_in[5];
    const float* b1   = (const float*)d_in[6];
    const float* W2   = (const float*)d_in[7];
    const float* b2   = (const float*)d_in[8];
    float* out = (float*)d_out;

    const int total4 = N_NODES * EMB / 4;
    const int init_blocks = (total4 + 255) / 256;           // 6250
    const int edge_blocks = (N_EDGES + 255) / 256;          // 5000
    const int node_blocks = (N_NODES + 255) / 256;          // 391
    const int layer_blocks = (N_NODES + 127) / 128;         // 782

    cudaFuncSetAttribute(k_layer_tc, cudaFuncAttributeMaxDynamicSharedMemorySize,
                         TC_SMEM);

    k_init<<<init_blocks, 256>>>(ue, ie, out);
    k_hist<<<edge_blocks, 256>>>(erow);
    k_scanA<<<NSCAN_BLOCKS, SCAN_BLK>>>();
    k_scanC<<<node_blocks, 256>>>();
    k_scatter<<<edge_blocks, 256>>>(erow, ecol, eval);

    for (int l = 0; l < 3; l++) {
        float scale = (l == 2) ? 0.25f : 1.0f;
        k_layer_tc<<<layer_blocks, 512, TC_SMEM>>>(
            W1 + l * EMB * EMB, b1 + l * EMB,
            W2 + l * EMB * EMB, b2 + l * EMB, out, scale, l & 1);
    }
}

// round 14
// speedup vs baseline: 1.0500x; 1.0500x over previous
#include <cuda_runtime.h>
#include <cuda_bf16.h>
#include <cstdint>

#define N_USERS 40000
#define N_ITEMS 60000
#define N_NODES 100000
#define N_EDGES 1280000
#define EMB 64
#define NEG_SLOPE 0.2f

#define SCAN_BLK 1024
#define NSCAN_BLOCKS ((N_NODES + SCAN_BLK - 1) / SCAN_BLK)   // 98

// ---------------- scratch ----------------
__device__ float g_e[N_NODES * EMB];
__device__ float g_x[N_NODES * EMB];
__device__ int   g_deg[N_NODES];
__device__ int   g_off[N_NODES];
__device__ int   g_head[N_NODES];
__device__ int   g_bsum[NSCAN_BLOCKS];
__device__ int2  g_csr_cv[N_EDGES];

// smem layout (bytes). K-stride = 136 bf16 = 272 B (16B shift/row)
#define KS 272
#define BB_OFF   0
#define SROW_OFF 256                         // 128 x 2 floats
#define AHI_OFF  1280
#define ALO_OFF  (AHI_OFF + 128 * KS)        // 36096
#define BHI_OFF  (ALO_OFF + 128 * KS)        // 70912
#define BLO_OFF  (BHI_OFF + 64 * KS)         // 88320
#define TC_SMEM  (BLO_OFF + 64 * KS)         // 105728

// ---------------------------------------------------------------------------
// helpers
// ---------------------------------------------------------------------------
__device__ __forceinline__ uint32_t packbf(float lo, float hi) {
    uint32_t r;
    asm("cvt.rn.bf16x2.f32 %0, %1, %2;" : "=r"(r) : "f"(hi), "f"(lo));
    return r;
}
__device__ __forceinline__ float bfhi(float x) {
    __nv_bfloat16 h = __float2bfloat16(x);
    return __bfloat162float(h);
}
__device__ __forceinline__ void mma_bf16(float* c, uint32_t a0, uint32_t a1,
                                         uint32_t a2, uint32_t a3,
                                         uint32_t b0, uint32_t b1) {
    asm volatile(
        "mma.sync.aligned.m16n8k16.row.col.f32.bf16.bf16.f32 "
        "{%0,%1,%2,%3}, {%4,%5,%6,%7}, {%8,%9}, {%0,%1,%2,%3};"
        : "+f"(c[0]), "+f"(c[1]), "+f"(c[2]), "+f"(c[3])
        : "r"(a0), "r"(a1), "r"(a2), "r"(a3), "r"(b0), "r"(b1));
}

// ---------------------------------------------------------------------------
// init / CSR build (known-good prelude)
// ---------------------------------------------------------------------------
__global__ void k_init(const float* __restrict__ ue, const float* __restrict__ ie,
                       float* __restrict__ out) {
    int i = blockIdx.x * blockDim.x + threadIdx.x;
    const int total4 = N_NODES * EMB / 4;
    if (i < N_NODES) g_deg[i] = 0;
    if (i >= total4) return;
    const int user4 = N_USERS * EMB / 4;
    float4 v;
    if (i < user4) v = ((const float4*)ue)[i];
    else           v = ((const float4*)ie)[i - user4];
    ((float4*)g_e)[i] = v;
    ((float4*)out)[i] = v;
}

__global__ void k_hist(const int* __restrict__ erow) {
    int i = blockIdx.x * blockDim.x + threadIdx.x;
    if (i < N_EDGES) atomicAdd(&g_deg[erow[i]], 1);
}

__global__ void __launch_bounds__(SCAN_BLK) k_scanA() {
    __shared__ int s[SCAN_BLK];
    int i = blockIdx.x * SCAN_BLK + threadIdx.x;
    int v = (i < N_NODES) ? g_deg[i] : 0;
    s[threadIdx.x] = v;
    __syncthreads();
    int inc = v;
    #pragma unroll
    for (int d = 1; d < SCAN_BLK; d <<= 1) {
        int t = (threadIdx.x >= d) ? s[threadIdx.x - d] : 0;
        __syncthreads();
        inc += t;
        s[threadIdx.x] = inc;
        __syncthreads();
    }
    if (i < N_NODES) g_off[i] = inc - v;
    if (threadIdx.x == SCAN_BLK - 1) g_bsum[blockIdx.x] = inc;
}

__global__ void __launch_bounds__(256) k_scanC() {
    __shared__ int s_carry;
    int sb = blockIdx.x >> 2;
    if (threadIdx.x < 32) {
        int sum = 0;
        for (int i = threadIdx.x; i < sb; i += 32) sum += g_bsum[i];
        #pragma unroll
        for (int d = 16; d; d >>= 1) sum += __shfl_xor_sync(0xffffffffu, sum, d);
        if (threadIdx.x == 0) s_carry = sum;
    }
    __syncthreads();
    int i = blockIdx.x * 256 + threadIdx.x;
    if (i >= N_NODES) return;
    int o = g_off[i] + s_carry;
    g_off[i] = o;
    g_head[i] = o;
}

__global__ void k_scatter(const int* __restrict__ erow, const int* __restrict__ ecol,
                          const float* __restrict__ eval) {
    int i = blockIdx.x * blockDim.x + threadIdx.x;
    if (i >= N_EDGES) return;
    int r = erow[i];
    int pos = atomicAdd(&g_head[r], 1);
    g_csr_cv[pos] = make_int2(ecol[i], __float_as_int(eval[i]));
}

// ---------------------------------------------------------------------------
// CSR SpMM (known 27us): x[n] = sum_j val_j * e[col_j]; 16 threads/node
// ---------------------------------------------------------------------------
__global__ void __launch_bounds__(256) k_spmm_csr() {
    int t = blockIdx.x * blockDim.x + threadIdx.x;
    int node = t >> 4;
    int c = t & 15;
    if (node >= N_NODES) return;
    int start = g_off[node];
    int deg = g_deg[node];

    float4 a0 = make_float4(0.f, 0.f, 0.f, 0.f);
    float4 a1 = make_float4(0.f, 0.f, 0.f, 0.f);
    int j = 0;
    for (; j + 3 < deg; j += 4) {
        int2 cv0 = g_csr_cv[start + j];
        int2 cv1 = g_csr_cv[start + j + 1];
        int2 cv2 = g_csr_cv[start + j + 2];
        int2 cv3 = g_csr_cv[start + j + 3];
        float4 f0 = __ldg(((const float4*)g_e) + cv0.x * 16 + c);
        float4 f1 = __ldg(((const float4*)g_e) + cv1.x * 16 + c);
        float4 f2 = __ldg(((const float4*)g_e) + cv2.x * 16 + c);
        float4 f3 = __ldg(((const float4*)g_e) + cv3.x * 16 + c);
        float v0 = __int_as_float(cv0.y), v1 = __int_as_float(cv1.y);
        float v2 = __int_as_float(cv2.y), v3 = __int_as_float(cv3.y);
        a0.x += v0 * f0.x; a0.y += v0 * f0.y; a0.z += v0 * f0.z; a0.w += v0 * f0.w;
        a1.x += v1 * f1.x; a1.y += v1 * f1.y; a1.z += v1 * f1.z; a1.w += v1 * f1.w;
        a0.x += v2 * f2.x; a0.y += v2 * f2.y; a0.z += v2 * f2.z; a0.w += v2 * f2.w;
        a1.x += v3 * f3.x; a1.y += v3 * f3.y; a1.z += v3 * f3.z; a1.w += v3 * f3.w;
    }
    for (; j < deg; j++) {
        int2 cv0 = g_csr_cv[start + j];
        float v0 = __int_as_float(cv0.y);
        float4 f0 = __ldg(((const float4*)g_e) + cv0.x * 16 + c);
        a0.x += v0 * f0.x; a0.y += v0 * f0.y; a0.z += v0 * f0.z; a0.w += v0 * f0.w;
    }
    a0.x += a1.x; a0.y += a1.y; a0.z += a1.z; a0.w += a1.w;
    ((float4*)g_x)[node * 16 + c] = a0;
}

// ---------------------------------------------------------------------------
// Tensor-core GEMM + epilogue (un-fused): 512 threads, 128 nodes/block.
// Reads own-node e,x (coalesced), builds A=[U|V] hi/lo + B=Wt hi/lo,
// D = A@B via 3-pass bf16 mma, bias+leaky+l2norm -> g_e, out=(out+e)*scale.
// ---------------------------------------------------------------------------
extern __shared__ char sm_tc[];

__global__ void __launch_bounds__(512, 2) k_gemm_tc(
    const float* __restrict__ W1, const float* __restrict__ b1,
    const float* __restrict__ W2, const float* __restrict__ b2,
    float* __restrict__ out, float scale) {

    char* sm = sm_tc;
    const int tid = threadIdx.x;
    const int w   = tid >> 5;
    const int l   = tid & 31;
    const int base = blockIdx.x * 128;

    // bias: threads 0..63
    if (tid < 64) ((float*)(sm + BB_OFF))[tid] = b1[tid] + b2[tid];

    // ---- build B tiles: Bt[n][k] = (k<64 ? W1[k][n] : W2[k-64][n]) ----
    {
        int n  = tid >> 3;        // 0..63
        int kq = tid & 7;         // 16-wide k block
        #pragma unroll
        for (int g = 0; g < 4; g++) {
            int k = kq * 16 + g * 4;
            float wv[4];
            #pragma unroll
            for (int c = 0; c < 4; c++) {
                int kk = k + c;
                wv[c] = (kk < 64) ? __ldg(W1 + kk * 64 + n)
                                  : __ldg(W2 + (kk - 64) * 64 + n);
            }
            float h0 = bfhi(wv[0]), h1 = bfhi(wv[1]), h2 = bfhi(wv[2]), h3 = bfhi(wv[3]);
            uint2 hi = make_uint2(packbf(h0, h1), packbf(h2, h3));
            uint2 lo = make_uint2(packbf(wv[0] - h0, wv[1] - h1),
                                  packbf(wv[2] - h2, wv[3] - h3));
            int off = n * KS + k * 2;
            *(uint2*)(sm + BHI_OFF + off) = hi;
            *(uint2*)(sm + BLO_OFF + off) = lo;
        }
    }

    // ---- build A tiles from own-node e,x (coalesced): 4 slices of 32 nodes ----
    #pragma unroll
    for (int it = 0; it < 4; it++) {
        int nd = (tid >> 4) + it * 32;     // local node 0..127
        int c  = tid & 15;                 // float4 chunk
        int node = base + nd;
        float4 ev = make_float4(0.f, 0.f, 0.f, 0.f);
        float4 xv = make_float4(0.f, 0.f, 0.f, 0.f);
        if (node < N_NODES) {
            ev = __ldg(((const float4*)g_e) + node * 16 + c);
            xv = __ldg(((const float4*)g_x) + node * 16 + c);
        }
        float4 u = make_float4(ev.x + xv.x, ev.y + xv.y, ev.z + xv.z, ev.w + xv.w);
        float4 v = make_float4(ev.x * xv.x, ev.y * xv.y, ev.z * xv.z, ev.w * xv.w);

        float uh0 = bfhi(u.x), uh1 = bfhi(u.y), uh2 = bfhi(u.z), uh3 = bfhi(u.w);
        float vh0 = bfhi(v.x), vh1 = bfhi(v.y), vh2 = bfhi(v.z), vh3 = bfhi(v.w);
        int offU = nd * KS + c * 8;          // k = 4c
        int offV = nd * KS + 128 + c * 8;    // k = 64 + 4c
        *(uint2*)(sm + AHI_OFF + offU) = make_uint2(packbf(uh0, uh1), packbf(uh2, uh3));
        *(uint2*)(sm + ALO_OFF + offU) = make_uint2(packbf(u.x - uh0, u.y - uh1),
                                                    packbf(u.z - uh2, u.w - uh3));
        *(uint2*)(sm + AHI_OFF + offV) = make_uint2(packbf(vh0, vh1), packbf(vh2, vh3));
        *(uint2*)(sm + ALO_OFF + offV) = make_uint2(packbf(v.x - vh0, v.y - vh1),
                                                    packbf(v.z - vh2, v.w - vh3));
    }
    __syncthreads();

    // ---- tensor-core GEMM ----
    const int wr = w >> 1;                 // row group 0..7
    const int wc = w & 1;                  // column half 0/1
    float acc[4][4];
    #pragma unroll
    for (int nt = 0; nt < 4; nt++)
        #pragma unroll
        for (int q = 0; q < 4; q++) acc[nt][q] = 0.f;

    const char* smAh = sm + AHI_OFF;
    const char* smAl = sm + ALO_OFF;
    const char* smBh = sm + BHI_OFF;
    const char* smBl = sm + BLO_OFF;
    const int rowA = (16 * wr + (l >> 2)) * KS;
    const int lk   = (l & 3) * 4;

    #pragma unroll
    for (int ks = 0; ks < 8; ks++) {
        int kb = ks * 32 + lk;
        uint32_t ah0 = *(const uint32_t*)(smAh + rowA + kb);
        uint32_t ah1 = *(const uint32_t*)(smAh + rowA + 8 * KS + kb);
        uint32_t ah2 = *(const uint32_t*)(smAh + rowA + kb + 16);
        uint32_t ah3 = *(const uint32_t*)(smAh + rowA + 8 * KS + kb + 16);
        uint32_t al0 = *(const uint32_t*)(smAl + rowA + kb);
        uint32_t al1 = *(const uint32_t*)(smAl + rowA + 8 * KS + kb);
        uint32_t al2 = *(const uint32_t*)(smAl + rowA + kb + 16);
        uint32_t al3 = *(const uint32_t*)(smAl + rowA + 8 * KS + kb + 16);
        #pragma unroll
        for (int nt = 0; nt < 4; nt++) {
            int rowB = (wc * 32 + nt * 8 + (l >> 2)) * KS + kb;
            uint32_t bh0 = *(const uint32_t*)(smBh + rowB);
            uint32_t bh1 = *(const uint32_t*)(smBh + rowB + 16);
            uint32_t bl0 = *(const uint32_t*)(smBl + rowB);
            uint32_t bl1 = *(const uint32_t*)(smBl + rowB + 16);
            mma_bf16(acc[nt], ah0, ah1, ah2, ah3, bh0, bh1);
            mma_bf16(acc[nt], ah0, ah1, ah2, ah3, bl0, bl1);
            mma_bf16(acc[nt], al0, al1, al2, al3, bh0, bh1);
        }
    }

    // ---- epilogue: bias + leaky, partial row sums, cross-warp combine ----
    const float* bb = (const float*)(sm + BB_OFF);
    float* srow = (float*)(sm + SROW_OFF);   // [128][2]
    float ss0 = 0.f, ss1 = 0.f;
    #pragma unroll
    for (int nt = 0; nt < 4; nt++) {
        int col0 = wc * 32 + nt * 8 + (l & 3) * 2;
        float bc0 = bb[col0], bc1 = bb[col0 + 1];
        float h;
        h = acc[nt][0] + bc0; h = (h >= 0.f) ? h : NEG_SLOPE * h; acc[nt][0] = h; ss0 += h * h;
        h = acc[nt][1] + bc1; h = (h >= 0.f) ? h : NEG_SLOPE * h; acc[nt][1] = h; ss0 += h * h;
        h = acc[nt][2] + bc0; h = (h >= 0.f) ? h : NEG_SLOPE * h; acc[nt][2] = h; ss1 += h * h;
        h = acc[nt][3] + bc1; h = (h >= 0.f) ? h : NEG_SLOPE * h; acc[nt][3] = h; ss1 += h * h;
    }
    ss0 += __shfl_xor_sync(0xffffffffu, ss0, 1);
    ss0 += __shfl_xor_sync(0xffffffffu, ss0, 2);
    ss1 += __shfl_xor_sync(0xffffffffu, ss1, 1);
    ss1 += __shfl_xor_sync(0xffffffffu, ss1, 2);

    int r0l = 16 * wr + (l >> 2);
    if ((l & 3) == 0) {
        srow[r0l * 2 + wc] = ss0;
        srow[(r0l + 8) * 2 + wc] = ss1;
    }
    __syncthreads();
    float inv0 = rsqrtf(fmaxf(srow[r0l * 2] + srow[r0l * 2 + 1], 1e-24f));
    float inv1 = rsqrtf(fmaxf(srow[(r0l + 8) * 2] + srow[(r0l + 8) * 2 + 1], 1e-24f));

    int r0 = base + r0l;
    int r1 = r0 + 8;
    if (r0 < N_NODES) {
        #pragma unroll
        for (int nt = 0; nt < 4; nt++) {
            int col0 = wc * 32 + nt * 8 + (l & 3) * 2;
            float e0 = acc[nt][0] * inv0, e1 = acc[nt][1] * inv0;
            *(float2*)(g_e + r0 * 64 + col0) = make_float2(e0, e1);
            float2 o = *(float2*)(out + r0 * 64 + col0);
            o.x = (o.x + e0) * scale;
            o.y = (o.y + e1) * scale;
            *(float2*)(out + r0 * 64 + col0) = o;
        }
    }
    if (r1 < N_NODES) {
        #pragma unroll
        for (int nt = 0; nt < 4; nt++) {
            int col0 = wc * 32 + nt * 8 + (l & 3) * 2;
            float e0 = acc[nt][2] * inv1, e1 = acc[nt][3] * inv1;
            *(float2*)(g_e + r1 * 64 + col0) = make_float2(e0, e1);
            float2 o = *(float2*)(out + r1 * 64 + col0);
            o.x = (o.x + e0) * scale;
            o.y = (o.y + e1) * scale;
            *(float2*)(out + r1 * 64 + col0) = o;
        }
    }
}

// ---------------------------------------------------------------------------
extern "C" void kernel_launch(void* const* d_in, const int* in_sizes, int n_in,
                              void* d_out, int out_size) {
    const int*   erow = (const int*)d_in[0];
    const int*   ecol = (const int*)d_in[1];
    const float* eval = (const float*)d_in[2];
    const float* ue   = (const float*)d_in[3];
    const float* ie   = (const float*)d_in[4];
    const float* W1   = (const float*)d_in[5];
    const float* b1   = (const float*)d_in[6];
    const float* W2   = (const float*)d_in[7];
    const float* b2   = (const float*)d_in[8];
    float* out = (float*)d_out;

    const int total4 = N_NODES * EMB / 4;
    const int init_blocks = (total4 + 255) / 256;           // 6250
    const int edge_blocks = (N_EDGES + 255) / 256;          // 5000
    const int node_blocks = (N_NODES + 255) / 256;          // 391
    const int spmm_blocks = (N_NODES * 16 + 255) / 256;     // 6250
    const int gemm_blocks = (N_NODES + 127) / 128;          // 782

    cudaFuncSetAttribute(k_gemm_tc, cudaFuncAttributeMaxDynamicSharedMemorySize,
                         TC_SMEM);

    k_init<<<init_blocks, 256>>>(ue, ie, out);
    k_hist<<<edge_blocks, 256>>>(erow);
    k_scanA<<<NSCAN_BLOCKS, SCAN_BLK>>>();
    k_scanC<<<node_blocks, 256>>>();
    k_scatter<<<edge_blocks, 256>>>(erow, ecol, eval);

    for (int l = 0; l < 3; l++) {
        k_spmm_csr<<<spmm_blocks, 256>>>();
        float scale = (l == 2) ? 0.25f : 1.0f;
        k_gemm_tc<<<gemm_blocks, 512, TC_SMEM>>>(
            W1 + l * EMB * EMB, b1 + l * EMB,
            W2 + l * EMB * EMB, b2 + l * EMB, out, scale);
    }
}

// round 15
// speedup vs baseline: 1.1250x; 1.0714x over previous
#include <cuda_runtime.h>
#include <cuda_bf16.h>
#include <cstdint>

#define N_USERS 40000
#define N_ITEMS 60000
#define N_NODES 100000
#define N_EDGES 1280000
#define EMB 64
#define NEG_SLOPE 0.2f

#define SCAN_BLK 1024
#define NSCAN_BLOCKS ((N_NODES + SCAN_BLK - 1) / SCAN_BLK)   // 98

// ---------------- scratch ----------------
__device__ float g_ea[N_NODES * EMB];
__device__ float g_eb[N_NODES * EMB];
__device__ int   g_deg[N_NODES];
__device__ int   g_off[N_NODES];
__device__ int   g_head[N_NODES];
__device__ int   g_bsum[NSCAN_BLOCKS];
__device__ int2  g_csr_cv[N_EDGES];

// smem layout (bytes). K-stride = 136 bf16 = 272 B (16B shift/row)
#define KS 272
#define BB_OFF   0
#define SROW_OFF 256                         // 128 x 2 floats
#define AHI_OFF  1280
#define ALO_OFF  (AHI_OFF + 128 * KS)        // 36096
#define BHI_OFF  (ALO_OFF + 128 * KS)        // 70912
#define BLO_OFF  (BHI_OFF + 64 * KS)         // 88320
#define TC_SMEM  (BLO_OFF + 64 * KS)         // 105728

// ---------------------------------------------------------------------------
// helpers
// ---------------------------------------------------------------------------
__device__ __forceinline__ uint32_t packbf(float lo, float hi) {
    uint32_t r;
    asm("cvt.rn.bf16x2.f32 %0, %1, %2;" : "=r"(r) : "f"(hi), "f"(lo));
    return r;
}
__device__ __forceinline__ float bfhi(float x) {
    __nv_bfloat16 h = __float2bfloat16(x);
    return __bfloat162float(h);
}
__device__ __forceinline__ void mma_bf16(float* c, uint32_t a0, uint32_t a1,
                                         uint32_t a2, uint32_t a3,
                                         uint32_t b0, uint32_t b1) {
    asm volatile(
        "mma.sync.aligned.m16n8k16.row.col.f32.bf16.bf16.f32 "
        "{%0,%1,%2,%3}, {%4,%5,%6,%7}, {%8,%9}, {%0,%1,%2,%3};"
        : "+f"(c[0]), "+f"(c[1]), "+f"(c[2]), "+f"(c[3])
        : "r"(a0), "r"(a1), "r"(a2), "r"(a3), "r"(b0), "r"(b1));
}
__device__ __forceinline__ void red_add_v2(float* p, float a, float b) {
    asm volatile("red.global.add.v2.f32 [%0], {%1, %2};"
                 :: "l"(p), "f"(a), "f"(b) : "memory");
}

// ---------------------------------------------------------------------------
// init: g_ea = concat(user_emb, item_emb); out = 0.25 * e0 ; deg = 0
// ---------------------------------------------------------------------------
__global__ void k_init(const float* __restrict__ ue, const float* __restrict__ ie,
                       float* __restrict__ out) {
    int i = blockIdx.x * blockDim.x + threadIdx.x;
    const int total4 = N_NODES * EMB / 4;
    if (i < N_NODES) g_deg[i] = 0;
    if (i >= total4) return;
    const int user4 = N_USERS * EMB / 4;
    float4 v;
    if (i < user4) v = ((const float4*)ue)[i];
    else           v = ((const float4*)ie)[i - user4];
    ((float4*)g_ea)[i] = v;
    ((float4*)out)[i] = make_float4(0.25f * v.x, 0.25f * v.y,
                                    0.25f * v.z, 0.25f * v.w);
}

__global__ void k_hist(const int* __restrict__ erow) {
    int i = blockIdx.x * blockDim.x + threadIdx.x;
    if (i < N_EDGES) atomicAdd(&g_deg[erow[i]], 1);
}

__global__ void __launch_bounds__(SCAN_BLK) k_scanA() {
    __shared__ int s[SCAN_BLK];
    int i = blockIdx.x * SCAN_BLK + threadIdx.x;
    int v = (i < N_NODES) ? g_deg[i] : 0;
    s[threadIdx.x] = v;
    __syncthreads();
    int inc = v;
    #pragma unroll
    for (int d = 1; d < SCAN_BLK; d <<= 1) {
        int t = (threadIdx.x >= d) ? s[threadIdx.x - d] : 0;
        __syncthreads();
        inc += t;
        s[threadIdx.x] = inc;
        __syncthreads();
    }
    if (i < N_NODES) g_off[i] = inc - v;
    if (threadIdx.x == SCAN_BLK - 1) g_bsum[blockIdx.x] = inc;
}

__global__ void __launch_bounds__(256) k_scanC() {
    __shared__ int s_carry;
    int sb = blockIdx.x >> 2;
    if (threadIdx.x < 32) {
        int sum = 0;
        for (int i = threadIdx.x; i < sb; i += 32) sum += g_bsum[i];
        #pragma unroll
        for (int d = 16; d; d >>= 1) sum += __shfl_xor_sync(0xffffffffu, sum, d);
        if (threadIdx.x == 0) s_carry = sum;
    }
    __syncthreads();
    int i = blockIdx.x * 256 + threadIdx.x;
    if (i >= N_NODES) return;
    int o = g_off[i] + s_carry;
    g_off[i] = o;
    g_head[i] = o;
}

// scatter: 2 edges/thread, independent atomic chains (MLP 2)
__global__ void k_scatter(const int* __restrict__ erow, const int* __restrict__ ecol,
                          const float* __restrict__ eval) {
    int i0 = blockIdx.x * (blockDim.x * 2) + threadIdx.x;
    int i1 = i0 + blockDim.x;
    int r0 = (i0 < N_EDGES) ? erow[i0] : -1;
    int r1 = (i1 < N_EDGES) ? erow[i1] : -1;
    int p0 = 0, p1 = 0;
    if (r0 >= 0) p0 = atomicAdd(&g_head[r0], 1);
    if (r1 >= 0) p1 = atomicAdd(&g_head[r1], 1);
    if (r0 >= 0) g_csr_cv[p0] = make_int2(ecol[i0], __float_as_int(eval[i0]));
    if (r1 >= 0) g_csr_cv[p1] = make_int2(ecol[i1], __float_as_int(eval[i1]));
}

// ---------------------------------------------------------------------------
// Fused layer (R12 structure), tensor-core GEMM, 512 threads, 128 nodes/block.
// gather x (CSR, fp32), build A=[U|V] hi/lo + B=Wt hi/lo,
// D = A@B (3-pass bf16 mma), bias+leaky+l2norm -> e_dst,
// out += 0.25*e  (red.global.add.v2, no read)
// ---------------------------------------------------------------------------
extern __shared__ char sm_tc[];

__global__ void __launch_bounds__(512, 2) k_layer_tc(
    const float* __restrict__ W1, const float* __restrict__ b1,
    const float* __restrict__ W2, const float* __restrict__ b2,
    float* __restrict__ out, int flag) {

    char* sm = sm_tc;
    const float* esrc = flag ? g_eb : g_ea;
    float*       edst = flag ? g_ea : g_eb;

    const int tid = threadIdx.x;
    const int w   = tid >> 5;
    const int l   = tid & 31;
    const int base = blockIdx.x * 128;

    // bias: threads 0..63
    if (tid < 64) ((float*)(sm + BB_OFF))[tid] = b1[tid] + b2[tid];

    // ---- build B tiles: Bt[n][k] = (k<64 ? W1[k][n] : W2[k-64][n]) ----
    {
        int n  = tid >> 3;        // 0..63
        int kq = tid & 7;         // 16-wide k block
        #pragma unroll
        for (int g = 0; g < 4; g++) {
            int k = kq * 16 + g * 4;
            float wv[4];
            #pragma unroll
            for (int c = 0; c < 4; c++) {
                int kk = k + c;
                wv[c] = (kk < 64) ? __ldg(W1 + kk * 64 + n)
                                  : __ldg(W2 + (kk - 64) * 64 + n);
            }
            float h0 = bfhi(wv[0]), h1 = bfhi(wv[1]), h2 = bfhi(wv[2]), h3 = bfhi(wv[3]);
            uint2 hi = make_uint2(packbf(h0, h1), packbf(h2, h3));
            uint2 lo = make_uint2(packbf(wv[0] - h0, wv[1] - h1),
                                  packbf(wv[2] - h2, wv[3] - h3));
            int off = n * KS + k * 2;
            *(uint2*)(sm + BHI_OFF + off) = hi;
            *(uint2*)(sm + BLO_OFF + off) = lo;
        }
    }

    // ---- gather + build A tiles: 4 slices of (32 nodes x 16 chunks) ----
    #pragma unroll 1
    for (int it = 0; it < 4; it++) {
        int nd = (tid >> 4) + it * 32;     // local node 0..127
        int c  = tid & 15;                 // float4 chunk
        int node = base + nd;
        float4 xa = make_float4(0.f, 0.f, 0.f, 0.f);
        float4 xb = make_float4(0.f, 0.f, 0.f, 0.f);
        float4 ev = make_float4(0.f, 0.f, 0.f, 0.f);
        if (node < N_NODES) {
            int start = g_off[node];
            int deg = g_deg[node];
            int j = 0;
            for (; j + 3 < deg; j += 4) {
                int2 cv0 = g_csr_cv[start + j];
                int2 cv1 = g_csr_cv[start + j + 1];
                int2 cv2 = g_csr_cv[start + j + 2];
                int2 cv3 = g_csr_cv[start + j + 3];
                float4 f0 = __ldg(((const float4*)esrc) + cv0.x * 16 + c);
                float4 f1 = __ldg(((const float4*)esrc) + cv1.x * 16 + c);
                float4 f2 = __ldg(((const float4*)esrc) + cv2.x * 16 + c);
                float4 f3 = __ldg(((const float4*)esrc) + cv3.x * 16 + c);
                float v0 = __int_as_float(cv0.y), v1 = __int_as_float(cv1.y);
                float v2 = __int_as_float(cv2.y), v3 = __int_as_float(cv3.y);
                xa.x += v0 * f0.x; xa.y += v0 * f0.y; xa.z += v0 * f0.z; xa.w += v0 * f0.w;
                xb.x += v1 * f1.x; xb.y += v1 * f1.y; xb.z += v1 * f1.z; xb.w += v1 * f1.w;
                xa.x += v2 * f2.x; xa.y += v2 * f2.y; xa.z += v2 * f2.z; xa.w += v2 * f2.w;
                xb.x += v3 * f3.x; xb.y += v3 * f3.y; xb.z += v3 * f3.z; xb.w += v3 * f3.w;
            }
            for (; j < deg; j++) {
                int2 cv0 = g_csr_cv[start + j];
                float v0 = __int_as_float(cv0.y);
                float4 f0 = __ldg(((const float4*)esrc) + cv0.x * 16 + c);
                xa.x += v0 * f0.x; xa.y += v0 * f0.y; xa.z += v0 * f0.z; xa.w += v0 * f0.w;
            }
            xa.x += xb.x; xa.y += xb.y; xa.z += xb.z; xa.w += xb.w;
            ev = __ldg(((const float4*)esrc) + node * 16 + c);
        }
        float4 u = make_float4(ev.x + xa.x, ev.y + xa.y, ev.z + xa.z, ev.w + xa.w);
        float4 v = make_float4(ev.x * xa.x, ev.y * xa.y, ev.z * xa.z, ev.w * xa.w);

        float uh0 = bfhi(u.x), uh1 = bfhi(u.y), uh2 = bfhi(u.z), uh3 = bfhi(u.w);
        float vh0 = bfhi(v.x), vh1 = bfhi(v.y), vh2 = bfhi(v.z), vh3 = bfhi(v.w);
        int offU = nd * KS + c * 8;          // k = 4c
        int offV = nd * KS + 128 + c * 8;    // k = 64 + 4c
        *(uint2*)(sm + AHI_OFF + offU) = make_uint2(packbf(uh0, uh1), packbf(uh2, uh3));
        *(uint2*)(sm + ALO_OFF + offU) = make_uint2(packbf(u.x - uh0, u.y - uh1),
                                                    packbf(u.z - uh2, u.w - uh3));
        *(uint2*)(sm + AHI_OFF + offV) = make_uint2(packbf(vh0, vh1), packbf(vh2, vh3));
        *(uint2*)(sm + ALO_OFF + offV) = make_uint2(packbf(v.x - vh0, v.y - vh1),
                                                    packbf(v.z - vh2, v.w - vh3));
    }
    __syncthreads();

    // ---- tensor-core GEMM ----
    const int wr = w >> 1;                 // row group 0..7
    const int wc = w & 1;                  // column half 0/1
    float acc[4][4];
    #pragma unroll
    for (int nt = 0; nt < 4; nt++)
        #pragma unroll
        for (int q = 0; q < 4; q++) acc[nt][q] = 0.f;

    const char* smAh = sm + AHI_OFF;
    const char* smAl = sm + ALO_OFF;
    const char* smBh = sm + BHI_OFF;
    const char* smBl = sm + BLO_OFF;
    const int rowA = (16 * wr + (l >> 2)) * KS;
    const int lk   = (l & 3) * 4;

    #pragma unroll
    for (int ks = 0; ks < 8; ks++) {
        int kb = ks * 32 + lk;
        uint32_t ah0 = *(const uint32_t*)(smAh + rowA + kb);
        uint32_t ah1 = *(const uint32_t*)(smAh + rowA + 8 * KS + kb);
        uint32_t ah2 = *(const uint32_t*)(smAh + rowA + kb + 16);
        uint32_t ah3 = *(const uint32_t*)(smAh + rowA + 8 * KS + kb + 16);
        uint32_t al0 = *(const uint32_t*)(smAl + rowA + kb);
        uint32_t al1 = *(const uint32_t*)(smAl + rowA + 8 * KS + kb);
        uint32_t al2 = *(const uint32_t*)(smAl + rowA + kb + 16);
        uint32_t al3 = *(const uint32_t*)(smAl + rowA + 8 * KS + kb + 16);
        #pragma unroll
        for (int nt = 0; nt < 4; nt++) {
            int rowB = (wc * 32 + nt * 8 + (l >> 2)) * KS + kb;
            uint32_t bh0 = *(const uint32_t*)(smBh + rowB);
            uint32_t bh1 = *(const uint32_t*)(smBh + rowB + 16);
            uint32_t bl0 = *(const uint32_t*)(smBl + rowB);
            uint32_t bl1 = *(const uint32_t*)(smBl + rowB + 16);
            mma_bf16(acc[nt], ah0, ah1, ah2, ah3, bh0, bh1);
            mma_bf16(acc[nt], ah0, ah1, ah2, ah3, bl0, bl1);
            mma_bf16(acc[nt], al0, al1, al2, al3, bh0, bh1);
        }
    }

    // ---- epilogue: bias + leaky, partial row sums, cross-warp combine ----
    const float* bb = (const float*)(sm + BB_OFF);
    float* srow = (float*)(sm + SROW_OFF);   // [128][2]
    float ss0 = 0.f, ss1 = 0.f;
    #pragma unroll
    for (int nt = 0; nt < 4; nt++) {
        int col0 = wc * 32 + nt * 8 + (l & 3) * 2;
        float bc0 = bb[col0], bc1 = bb[col0 + 1];
        float h;
        h = acc[nt][0] + bc0; h = (h >= 0.f) ? h : NEG_SLOPE * h; acc[nt][0] = h; ss0 += h * h;
        h = acc[nt][1] + bc1; h = (h >= 0.f) ? h : NEG_SLOPE * h; acc[nt][1] = h; ss0 += h * h;
        h = acc[nt][2] + bc0; h = (h >= 0.f) ? h : NEG_SLOPE * h; acc[nt][2] = h; ss1 += h * h;
        h = acc[nt][3] + bc1; h = (h >= 0.f) ? h : NEG_SLOPE * h; acc[nt][3] = h; ss1 += h * h;
    }
    ss0 += __shfl_xor_sync(0xffffffffu, ss0, 1);
    ss0 += __shfl_xor_sync(0xffffffffu, ss0, 2);
    ss1 += __shfl_xor_sync(0xffffffffu, ss1, 1);
    ss1 += __shfl_xor_sync(0xffffffffu, ss1, 2);

    int r0l = 16 * wr + (l >> 2);
    if ((l & 3) == 0) {
        srow[r0l * 2 + wc] = ss0;
        srow[(r0l + 8) * 2 + wc] = ss1;
    }
    __syncthreads();
    float inv0 = rsqrtf(fmaxf(srow[r0l * 2] + srow[r0l * 2 + 1], 1e-24f));
    float inv1 = rsqrtf(fmaxf(srow[(r0l + 8) * 2] + srow[(r0l + 8) * 2 + 1], 1e-24f));

    int r0 = base + r0l;
    int r1 = r0 + 8;
    if (r0 < N_NODES) {
        #pragma unroll
        for (int nt = 0; nt < 4; nt++) {
            int col0 = wc * 32 + nt * 8 + (l & 3) * 2;
            float e0 = acc[nt][0] * inv0, e1 = acc[nt][1] * inv0;
            *(float2*)(edst + r0 * 64 + col0) = make_float2(e0, e1);
            red_add_v2(out + r0 * 64 + col0, 0.25f * e0, 0.25f * e1);
        }
    }
    if (r1 < N_NODES) {
        #pragma unroll
        for (int nt = 0; nt < 4; nt++) {
            int col0 = wc * 32 + nt * 8 + (l & 3) * 2;
            float e0 = acc[nt][2] * inv1, e1 = acc[nt][3] * inv1;
            *(float2*)(edst + r1 * 64 + col0) = make_float2(e0, e1);
            red_add_v2(out + r1 * 64 + col0, 0.25f * e0, 0.25f * e1);
        }
    }
}

// ---------------------------------------------------------------------------
extern "C" void kernel_launch(void* const* d_in, const int* in_sizes, int n_in,
                              void* d_out, int out_size) {
    const int*   erow = (const int*)d_in[0];
    const int*   ecol = (const int*)d_in[1];
    const float* eval = (const float*)d_in[2];
    const float* ue   = (const float*)d_in[3];
    const float* ie   = (const float*)d_in[4];
    const float* W1   = (const float*)d_in[5];
    const float* b1   = (const float*)d_in[6];
    const float* W2   = (const float*)d_in[7];
    const float* b2   = (const float*)d_in[8];
    float* out = (float*)d_out;

    const int total4 = N_NODES * EMB / 4;
    const int init_blocks = (total4 + 255) / 256;           // 6250
    const int edge_blocks = (N_EDGES + 255) / 256;          // 5000
    const int edge2_blocks = (N_EDGES + 511) / 512;         // 2500
    const int node_blocks = (N_NODES + 255) / 256;          // 391
    const int layer_blocks = (N_NODES + 127) / 128;         // 782

    cudaFuncSetAttribute(k_layer_tc, cudaFuncAttributeMaxDynamicSharedMemorySize,
                         TC_SMEM);

    k_init<<<init_blocks, 256>>>(ue, ie, out);
    k_hist<<<edge_blocks, 256>>>(erow);
    k_scanA<<<NSCAN_BLOCKS, SCAN_BLK>>>();
    k_scanC<<<node_blocks, 256>>>();
    k_scatter<<<edge2_blocks, 256>>>(erow, ecol, eval);

    for (int l = 0; l < 3; l++) {
        k_layer_tc<<<layer_blocks, 512, TC_SMEM>>>(
            W1 + l * EMB * EMB, b1 + l * EMB,
            W2 + l * EMB * EMB, b2 + l * EMB, out, l & 1);
    }
}

// round 16
// speedup vs baseline: 1.1312x; 1.0055x over previous
#include <cuda_runtime.h>
#include <cuda_bf16.h>
#include <cstdint>

#define N_USERS 40000
#define N_ITEMS 60000
#define N_NODES 100000
#define N_EDGES 1280000
#define EMB 64
#define NEG_SLOPE 0.2f
#define PAD 64                     // bucket entries per node

#define INIT_BLOCKS ((N_NODES * EMB / 4 + 255) / 256)       // 6250
#define SCAT_BLOCKS ((N_EDGES + 511) / 512)                 // 2500

// ---------------- scratch ----------------
__device__ float g_ea[N_NODES * EMB];
__device__ float g_eb[N_NODES * EMB];
__device__ int   g_head[N_NODES];          // zero at load; re-zeroed by last layer
__device__ int2  g_pad[N_NODES * PAD];     // bucketed (col, val) records, 51.2MB

// smem layout (bytes). K-stride = 136 bf16 = 272 B (16B shift/row)
#define KS 272
#define BB_OFF   0
#define SROW_OFF 256                         // 128 x 2 floats
#define AHI_OFF  1280
#define ALO_OFF  (AHI_OFF + 128 * KS)        // 36096
#define BHI_OFF  (ALO_OFF + 128 * KS)        // 70912
#define BLO_OFF  (BHI_OFF + 64 * KS)         // 88320
#define TC_SMEM  (BLO_OFF + 64 * KS)         // 105728

// ---------------------------------------------------------------------------
// helpers
// ---------------------------------------------------------------------------
__device__ __forceinline__ uint32_t packbf(float lo, float hi) {
    uint32_t r;
    asm("cvt.rn.bf16x2.f32 %0, %1, %2;" : "=r"(r) : "f"(hi), "f"(lo));
    return r;
}
__device__ __forceinline__ float bfhi(float x) {
    __nv_bfloat16 h = __float2bfloat16(x);
    return __bfloat162float(h);
}
__device__ __forceinline__ void mma_bf16(float* c, uint32_t a0, uint32_t a1,
                                         uint32_t a2, uint32_t a3,
                                         uint32_t b0, uint32_t b1) {
    asm volatile(
        "mma.sync.aligned.m16n8k16.row.col.f32.bf16.bf16.f32 "
        "{%0,%1,%2,%3}, {%4,%5,%6,%7}, {%8,%9}, {%0,%1,%2,%3};"
        : "+f"(c[0]), "+f"(c[1]), "+f"(c[2]), "+f"(c[3])
        : "r"(a0), "r"(a1), "r"(a2), "r"(a3), "r"(b0), "r"(b1));
}
__device__ __forceinline__ void red_add_v2(float* p, float a, float b) {
    asm volatile("red.global.add.v2.f32 [%0], {%1, %2};"
                 :: "l"(p), "f"(a), "f"(b) : "memory");
}

// ---------------------------------------------------------------------------
// prelude: blocks [0, INIT_BLOCKS) -> e/out init;
//          blocks [INIT_BLOCKS, +SCAT_BLOCKS) -> bucket scatter (2 edges/thr).
// g_head is zero on entry (module-load zero-init / re-zeroed by last layer).
// ---------------------------------------------------------------------------
__global__ void k_prelude(const int* __restrict__ erow, const int* __restrict__ ecol,
                          const float* __restrict__ eval,
                          const float* __restrict__ ue, const float* __restrict__ ie,
                          float* __restrict__ out) {
    int b = blockIdx.x;
    if (b < INIT_BLOCKS) {
        int i = b * 256 + threadIdx.x;
        const int total4 = N_NODES * EMB / 4;
        if (i >= total4) return;
        const int user4 = N_USERS * EMB / 4;
        float4 v;
        if (i < user4) v = ((const float4*)ue)[i];
        else           v = ((const float4*)ie)[i - user4];
        ((float4*)g_ea)[i] = v;
        ((float4*)out)[i] = make_float4(0.25f * v.x, 0.25f * v.y,
                                        0.25f * v.z, 0.25f * v.w);
    } else {
        int i0 = (b - INIT_BLOCKS) * 512 + threadIdx.x;
        int i1 = i0 + 256;
        int r0 = (i0 < N_EDGES) ? erow[i0] : -1;
        int r1 = (i1 < N_EDGES) ? erow[i1] : -1;
        int p0 = PAD, p1 = PAD;
        if (r0 >= 0) p0 = atomicAdd(&g_head[r0], 1);
        if (r1 >= 0) p1 = atomicAdd(&g_head[r1], 1);
        if (r0 >= 0 && p0 < PAD)
            g_pad[r0 * PAD + p0] = make_int2(ecol[i0], __float_as_int(eval[i0]));
        if (r1 >= 0 && p1 < PAD)
            g_pad[r1 * PAD + p1] = make_int2(ecol[i1], __float_as_int(eval[i1]));
    }
}

// ---------------------------------------------------------------------------
// Fused layer (R15 structure): gather x from buckets, build A=[U|V] hi/lo +
// B=Wt hi/lo, D = A@B (3-pass bf16 mma), bias+leaky+l2norm -> e_dst,
// out += 0.25*e (red.global.add.v2). Last layer re-zeroes g_head.
// 512 threads, 128 nodes/block.
// ---------------------------------------------------------------------------
extern __shared__ char sm_tc[];

__global__ void __launch_bounds__(512, 2) k_layer_tc(
    const float* __restrict__ W1, const float* __restrict__ b1,
    const float* __restrict__ W2, const float* __restrict__ b2,
    float* __restrict__ out, int flag, int last) {

    char* sm = sm_tc;
    const float* esrc = flag ? g_eb : g_ea;
    float*       edst = flag ? g_ea : g_eb;

    const int tid = threadIdx.x;
    const int w   = tid >> 5;
    const int l   = tid & 31;
    const int base = blockIdx.x * 128;

    // bias: threads 0..63
    if (tid < 64) ((float*)(sm + BB_OFF))[tid] = b1[tid] + b2[tid];

    // ---- build B tiles: Bt[n][k] = (k<64 ? W1[k][n] : W2[k-64][n]) ----
    {
        int n  = tid >> 3;        // 0..63
        int kq = tid & 7;         // 16-wide k block
        #pragma unroll
        for (int g = 0; g < 4; g++) {
            int k = kq * 16 + g * 4;
            float wv[4];
            #pragma unroll
            for (int c = 0; c < 4; c++) {
                int kk = k + c;
                wv[c] = (kk < 64) ? __ldg(W1 + kk * 64 + n)
                                  : __ldg(W2 + (kk - 64) * 64 + n);
            }
            float h0 = bfhi(wv[0]), h1 = bfhi(wv[1]), h2 = bfhi(wv[2]), h3 = bfhi(wv[3]);
            uint2 hi = make_uint2(packbf(h0, h1), packbf(h2, h3));
            uint2 lo = make_uint2(packbf(wv[0] - h0, wv[1] - h1),
                                  packbf(wv[2] - h2, wv[3] - h3));
            int off = n * KS + k * 2;
            *(uint2*)(sm + BHI_OFF + off) = hi;
            *(uint2*)(sm + BLO_OFF + off) = lo;
        }
    }

    // ---- gather + build A tiles: 4 slices of (32 nodes x 16 chunks) ----
    #pragma unroll 1
    for (int it = 0; it < 4; it++) {
        int nd = (tid >> 4) + it * 32;     // local node 0..127
        int c  = tid & 15;                 // float4 chunk
        int node = base + nd;
        float4 xa = make_float4(0.f, 0.f, 0.f, 0.f);
        float4 xb = make_float4(0.f, 0.f, 0.f, 0.f);
        float4 ev = make_float4(0.f, 0.f, 0.f, 0.f);
        if (node < N_NODES) {
            int start = node * PAD;
            int deg = g_head[node];
            if (deg > PAD) deg = PAD;
            int j = 0;
            for (; j + 3 < deg; j += 4) {
                int2 cv0 = g_pad[start + j];
                int2 cv1 = g_pad[start + j + 1];
                int2 cv2 = g_pad[start + j + 2];
                int2 cv3 = g_pad[start + j + 3];
                float4 f0 = __ldg(((const float4*)esrc) + cv0.x * 16 + c);
                float4 f1 = __ldg(((const float4*)esrc) + cv1.x * 16 + c);
                float4 f2 = __ldg(((const float4*)esrc) + cv2.x * 16 + c);
                float4 f3 = __ldg(((const float4*)esrc) + cv3.x * 16 + c);
                float v0 = __int_as_float(cv0.y), v1 = __int_as_float(cv1.y);
                float v2 = __int_as_float(cv2.y), v3 = __int_as_float(cv3.y);
                xa.x += v0 * f0.x; xa.y += v0 * f0.y; xa.z += v0 * f0.z; xa.w += v0 * f0.w;
                xb.x += v1 * f1.x; xb.y += v1 * f1.y; xb.z += v1 * f1.z; xb.w += v1 * f1.w;
                xa.x += v2 * f2.x; xa.y += v2 * f2.y; xa.z += v2 * f2.z; xa.w += v2 * f2.w;
                xb.x += v3 * f3.x; xb.y += v3 * f3.y; xb.z += v3 * f3.z; xb.w += v3 * f3.w;
            }
            for (; j < deg; j++) {
                int2 cv0 = g_pad[start + j];
                float v0 = __int_as_float(cv0.y);
                float4 f0 = __ldg(((const float4*)esrc) + cv0.x * 16 + c);
                xa.x += v0 * f0.x; xa.y += v0 * f0.y; xa.z += v0 * f0.z; xa.w += v0 * f0.w;
            }
            xa.x += xb.x; xa.y += xb.y; xa.z += xb.z; xa.w += xb.w;
            ev = __ldg(((const float4*)esrc) + node * 16 + c);
        }
        float4 u = make_float4(ev.x + xa.x, ev.y + xa.y, ev.z + xa.z, ev.w + xa.w);
        float4 v = make_float4(ev.x * xa.x, ev.y * xa.y, ev.z * xa.z, ev.w * xa.w);

        float uh0 = bfhi(u.x), uh1 = bfhi(u.y), uh2 = bfhi(u.z), uh3 = bfhi(u.w);
        float vh0 = bfhi(v.x), vh1 = bfhi(v.y), vh2 = bfhi(v.z), vh3 = bfhi(v.w);
        int offU = nd * KS + c * 8;          // k = 4c
        int offV = nd * KS + 128 + c * 8;    // k = 64 + 4c
        *(uint2*)(sm + AHI_OFF + offU) = make_uint2(packbf(uh0, uh1), packbf(uh2, uh3));
        *(uint2*)(sm + ALO_OFF + offU) = make_uint2(packbf(u.x - uh0, u.y - uh1),
                                                    packbf(u.z - uh2, u.w - uh3));
        *(uint2*)(sm + AHI_OFF + offV) = make_uint2(packbf(vh0, vh1), packbf(vh2, vh3));
        *(uint2*)(sm + ALO_OFF + offV) = make_uint2(packbf(v.x - vh0, v.y - vh1),
                                                    packbf(v.z - vh2, v.w - vh3));
    }
    __syncthreads();   // all gather reads (incl. g_head) complete past this point

    // ---- tensor-core GEMM ----
    const int wr = w >> 1;                 // row group 0..7
    const int wc = w & 1;                  // column half 0/1
    float acc[4][4];
    #pragma unroll
    for (int nt = 0; nt < 4; nt++)
        #pragma unroll
        for (int q = 0; q < 4; q++) acc[nt][q] = 0.f;

    const char* smAh = sm + AHI_OFF;
    const char* smAl = sm + ALO_OFF;
    const char* smBh = sm + BHI_OFF;
    const char* smBl = sm + BLO_OFF;
    const int rowA = (16 * wr + (l >> 2)) * KS;
    const int lk   = (l & 3) * 4;

    #pragma unroll
    for (int ks = 0; ks < 8; ks++) {
        int kb = ks * 32 + lk;
        uint32_t ah0 = *(const uint32_t*)(smAh + rowA + kb);
        uint32_t ah1 = *(const uint32_t*)(smAh + rowA + 8 * KS + kb);
        uint32_t ah2 = *(const uint32_t*)(smAh + rowA + kb + 16);
        uint32_t ah3 = *(const uint32_t*)(smAh + rowA + 8 * KS + kb + 16);
        uint32_t al0 = *(const uint32_t*)(smAl + rowA + kb);
        uint32_t al1 = *(const uint32_t*)(smAl + rowA + 8 * KS + kb);
        uint32_t al2 = *(const uint32_t*)(smAl + rowA + kb + 16);
        uint32_t al3 = *(const uint32_t*)(smAl + rowA + 8 * KS + kb + 16);
        #pragma unroll
        for (int nt = 0; nt < 4; nt++) {
            int rowB = (wc * 32 + nt * 8 + (l >> 2)) * KS + kb;
            uint32_t bh0 = *(const uint32_t*)(smBh + rowB);
            uint32_t bh1 = *(const uint32_t*)(smBh + rowB + 16);
            uint32_t bl0 = *(const uint32_t*)(smBl + rowB);
            uint32_t bl1 = *(const uint32_t*)(smBl + rowB + 16);
            mma_bf16(acc[nt], ah0, ah1, ah2, ah3, bh0, bh1);
            mma_bf16(acc[nt], ah0, ah1, ah2, ah3, bl0, bl1);
            mma_bf16(acc[nt], al0, al1, al2, al3, bh0, bh1);
        }
    }

    // last layer: reset bucket heads for the next graph replay
    if (last && tid < 128) {
        int node = base + tid;
        if (node < N_NODES) g_head[node] = 0;
    }

    // ---- epilogue: bias + leaky, partial row sums, cross-warp combine ----
    const float* bb = (const float*)(sm + BB_OFF);
    float* srow = (float*)(sm + SROW_OFF);   // [128][2]
    float ss0 = 0.f, ss1 = 0.f;
    #pragma unroll
    for (int nt = 0; nt < 4; nt++) {
        int col0 = wc * 32 + nt * 8 + (l & 3) * 2;
        float bc0 = bb[col0], bc1 = bb[col0 + 1];
        float h;
        h = acc[nt][0] + bc0; h = (h >= 0.f) ? h : NEG_SLOPE * h; acc[nt][0] = h; ss0 += h * h;
        h = acc[nt][1] + bc1; h = (h >= 0.f) ? h : NEG_SLOPE * h; acc[nt][1] = h; ss0 += h * h;
        h = acc[nt][2] + bc0; h = (h >= 0.f) ? h : NEG_SLOPE * h; acc[nt][2] = h; ss1 += h * h;
        h = acc[nt][3] + bc1; h = (h >= 0.f) ? h : NEG_SLOPE * h; acc[nt][3] = h; ss1 += h * h;
    }
    ss0 += __shfl_xor_sync(0xffffffffu, ss0, 1);
    ss0 += __shfl_xor_sync(0xffffffffu, ss0, 2);
    ss1 += __shfl_xor_sync(0xffffffffu, ss1, 1);
    ss1 += __shfl_xor_sync(0xffffffffu, ss1, 2);

    int r0l = 16 * wr + (l >> 2);
    if ((l & 3) == 0) {
        srow[r0l * 2 + wc] = ss0;
        srow[(r0l + 8) * 2 + wc] = ss1;
    }
    __syncthreads();
    float inv0 = rsqrtf(fmaxf(srow[r0l * 2] + srow[r0l * 2 + 1], 1e-24f));
    float inv1 = rsqrtf(fmaxf(srow[(r0l + 8) * 2] + srow[(r0l + 8) * 2 + 1], 1e-24f));

    int r0 = base + r0l;
    int r1 = r0 + 8;
    if (r0 < N_NODES) {
        #pragma unroll
        for (int nt = 0; nt < 4; nt++) {
            int col0 = wc * 32 + nt * 8 + (l & 3) * 2;
            float e0 = acc[nt][0] * inv0, e1 = acc[nt][1] * inv0;
            *(float2*)(edst + r0 * 64 + col0) = make_float2(e0, e1);
            red_add_v2(out + r0 * 64 + col0, 0.25f * e0, 0.25f * e1);
        }
    }
    if (r1 < N_NODES) {
        #pragma unroll
        for (int nt = 0; nt < 4; nt++) {
            int col0 = wc * 32 + nt * 8 + (l & 3) * 2;
            float e0 = acc[nt][2] * inv1, e1 = acc[nt][3] * inv1;
            *(float2*)(edst + r1 * 64 + col0) = make_float2(e0, e1);
            red_add_v2(out + r1 * 64 + col0, 0.25f * e0, 0.25f * e1);
        }
    }
}

// ---------------------------------------------------------------------------
extern "C" void kernel_launch(void* const* d_in, const int* in_sizes, int n_in,
                              void* d_out, int out_size) {
    const int*   erow = (const int*)d_in[0];
    const int*   ecol = (const int*)d_in[1];
    const float* eval = (const float*)d_in[2];
    const float* ue   = (const float*)d_in[3];
    const float* ie   = (const float*)d_in[4];
    const float* W1   = (const float*)d_in[5];
    const float* b1   = (const float*)d_in[6];
    const float* W2   = (const float*)d_in[7];
    const float* b2   = (const float*)d_in[8];
    float* out = (float*)d_out;

    const int prelude_blocks = INIT_BLOCKS + SCAT_BLOCKS;   // 8750
    const int layer_blocks = (N_NODES + 127) / 128;         // 782

    cudaFuncSetAttribute(k_layer_tc, cudaFuncAttributeMaxDynamicSharedMemorySize,
                         TC_SMEM);

    k_prelude<<<prelude_blocks, 256>>>(erow, ecol, eval, ue, ie, out);

    for (int l = 0; l < 3; l++) {
        k_layer_tc<<<layer_blocks, 512, TC_SMEM>>>(
            W1 + l * EMB * EMB, b1 + l * EMB,
            W2 + l * EMB * EMB, b2 + l * EMB, out, l & 1, l == 2);
    }
}

// round 17
// speedup vs baseline: 1.1667x; 1.0314x over previous
#include <cuda_runtime.h>
#include <cuda_bf16.h>
#include <cstdint>

#define N_USERS 40000
#define N_ITEMS 60000
#define N_NODES 100000
#define N_EDGES 1280000
#define EMB 64
#define NEG_SLOPE 0.2f
#define PAD 64                     // bucket entries per node
#define N_TILES ((N_NODES + 127) / 128)     // 782
#define PERSIST_BLOCKS 296                  // 2 per SM x 148 SMs

#define INIT_BLOCKS ((N_NODES * EMB / 4 + 255) / 256)       // 6250
#define SCAT_BLOCKS ((N_EDGES + 511) / 512)                 // 2500

// ---------------- scratch ----------------
__device__ float g_ea[N_NODES * EMB];
__device__ float g_eb[N_NODES * EMB];
__device__ int   g_head[N_NODES];          // zero at load; re-zeroed by last layer
__device__ int2  g_pad[N_NODES * PAD];     // bucketed (col, val) records, 51.2MB

// smem layout (bytes). K-stride = 136 bf16 = 272 B (16B shift/row)
#define KS 272
#define BB_OFF   0
#define SROW_OFF 256                         // 128 x 2 floats
#define AHI_OFF  1280
#define ALO_OFF  (AHI_OFF + 128 * KS)        // 36096
#define BHI_OFF  (ALO_OFF + 128 * KS)        // 70912
#define BLO_OFF  (BHI_OFF + 64 * KS)         // 88320
#define TC_SMEM  (BLO_OFF + 64 * KS)         // 105728

// ---------------------------------------------------------------------------
// helpers
// ---------------------------------------------------------------------------
__device__ __forceinline__ uint32_t packbf(float lo, float hi) {
    uint32_t r;
    asm("cvt.rn.bf16x2.f32 %0, %1, %2;" : "=r"(r) : "f"(hi), "f"(lo));
    return r;
}
__device__ __forceinline__ float bfhi(float x) {
    __nv_bfloat16 h = __float2bfloat16(x);
    return __bfloat162float(h);
}
__device__ __forceinline__ void mma_bf16(float* c, uint32_t a0, uint32_t a1,
                                         uint32_t a2, uint32_t a3,
                                         uint32_t b0, uint32_t b1) {
    asm volatile(
        "mma.sync.aligned.m16n8k16.row.col.f32.bf16.bf16.f32 "
        "{%0,%1,%2,%3}, {%4,%5,%6,%7}, {%8,%9}, {%0,%1,%2,%3};"
        : "+f"(c[0]), "+f"(c[1]), "+f"(c[2]), "+f"(c[3])
        : "r"(a0), "r"(a1), "r"(a2), "r"(a3), "r"(b0), "r"(b1));
}
__device__ __forceinline__ void red_add_v2(float* p, float a, float b) {
    asm volatile("red.global.add.v2.f32 [%0], {%1, %2};"
                 :: "l"(p), "f"(a), "f"(b) : "memory");
}

// ---------------------------------------------------------------------------
// prelude: blocks [0, INIT_BLOCKS) -> e/out init;
//          blocks [INIT_BLOCKS, +SCAT_BLOCKS) -> bucket scatter (2 edges/thr).
// ---------------------------------------------------------------------------
__global__ void k_prelude(const int* __restrict__ erow, const int* __restrict__ ecol,
                          const float* __restrict__ eval,
                          const float* __restrict__ ue, const float* __restrict__ ie,
                          float* __restrict__ out) {
    int b = blockIdx.x;
    if (b < INIT_BLOCKS) {
        int i = b * 256 + threadIdx.x;
        const int total4 = N_NODES * EMB / 4;
        if (i >= total4) return;
        const int user4 = N_USERS * EMB / 4;
        float4 v;
        if (i < user4) v = ((const float4*)ue)[i];
        else           v = ((const float4*)ie)[i - user4];
        ((float4*)g_ea)[i] = v;
        ((float4*)out)[i] = make_float4(0.25f * v.x, 0.25f * v.y,
                                        0.25f * v.z, 0.25f * v.w);
    } else {
        int i0 = (b - INIT_BLOCKS) * 512 + threadIdx.x;
        int i1 = i0 + 256;
        int r0 = (i0 < N_EDGES) ? erow[i0] : -1;
        int r1 = (i1 < N_EDGES) ? erow[i1] : -1;
        int p0 = PAD, p1 = PAD;
        if (r0 >= 0) p0 = atomicAdd(&g_head[r0], 1);
        if (r1 >= 0) p1 = atomicAdd(&g_head[r1], 1);
        if (r0 >= 0 && p0 < PAD)
            g_pad[r0 * PAD + p0] = make_int2(ecol[i0], __float_as_int(eval[i0]));
        if (r1 >= 0 && p1 < PAD)
            g_pad[r1 * PAD + p1] = make_int2(ecol[i1], __float_as_int(eval[i1]));
    }
}

// ---------------------------------------------------------------------------
// Persistent fused layer: 296 blocks, each loops over tiles (stride 296).
// B tiles + bias built ONCE per block. Per tile: gather -> mma -> epilogue.
// ---------------------------------------------------------------------------
extern __shared__ char sm_tc[];

__global__ void __launch_bounds__(512, 2) k_layer_tc(
    const float* __restrict__ W1, const float* __restrict__ b1,
    const float* __restrict__ W2, const float* __restrict__ b2,
    float* __restrict__ out, int flag, int last) {

    char* sm = sm_tc;
    const float* esrc = flag ? g_eb : g_ea;
    float*       edst = flag ? g_ea : g_eb;

    const int tid = threadIdx.x;
    const int w   = tid >> 5;
    const int l   = tid & 31;

    // bias: threads 0..63 (once)
    if (tid < 64) ((float*)(sm + BB_OFF))[tid] = b1[tid] + b2[tid];

    // ---- build B tiles once: Bt[n][k] = (k<64 ? W1[k][n] : W2[k-64][n]) ----
    {
        int n  = tid >> 3;        // 0..63
        int kq = tid & 7;         // 16-wide k block
        #pragma unroll
        for (int g = 0; g < 4; g++) {
            int k = kq * 16 + g * 4;
            float wv[4];
            #pragma unroll
            for (int c = 0; c < 4; c++) {
                int kk = k + c;
                wv[c] = (kk < 64) ? __ldg(W1 + kk * 64 + n)
                                  : __ldg(W2 + (kk - 64) * 64 + n);
            }
            float h0 = bfhi(wv[0]), h1 = bfhi(wv[1]), h2 = bfhi(wv[2]), h3 = bfhi(wv[3]);
            uint2 hi = make_uint2(packbf(h0, h1), packbf(h2, h3));
            uint2 lo = make_uint2(packbf(wv[0] - h0, wv[1] - h1),
                                  packbf(wv[2] - h2, wv[3] - h3));
            int off = n * KS + k * 2;
            *(uint2*)(sm + BHI_OFF + off) = hi;
            *(uint2*)(sm + BLO_OFF + off) = lo;
        }
    }

    const int wr = w >> 1;                 // row group 0..7
    const int wc = w & 1;                  // column half 0/1
    const char* smAh = sm + AHI_OFF;
    const char* smAl = sm + ALO_OFF;
    const char* smBh = sm + BHI_OFF;
    const char* smBl = sm + BLO_OFF;
    const float* bb = (const float*)(sm + BB_OFF);
    float* srow = (float*)(sm + SROW_OFF);   // [128][2]
    const int rowA = (16 * wr + (l >> 2)) * KS;
    const int lk   = (l & 3) * 4;

    for (int tile = blockIdx.x; tile < N_TILES; tile += PERSIST_BLOCKS) {
        const int base = tile * 128;

        // ---- gather + build A tiles: 4 slices of (32 nodes x 16 chunks) ----
        #pragma unroll 1
        for (int it = 0; it < 4; it++) {
            int nd = (tid >> 4) + it * 32;     // local node 0..127
            int c  = tid & 15;                 // float4 chunk
            int node = base + nd;
            float4 xa = make_float4(0.f, 0.f, 0.f, 0.f);
            float4 xb = make_float4(0.f, 0.f, 0.f, 0.f);
            float4 ev = make_float4(0.f, 0.f, 0.f, 0.f);
            if (node < N_NODES) {
                int start = node * PAD;
                int deg = g_head[node];
                if (deg > PAD) deg = PAD;
                int j = 0;
                for (; j + 3 < deg; j += 4) {
                    int2 cv0 = g_pad[start + j];
                    int2 cv1 = g_pad[start + j + 1];
                    int2 cv2 = g_pad[start + j + 2];
                    int2 cv3 = g_pad[start + j + 3];
                    float4 f0 = __ldg(((const float4*)esrc) + cv0.x * 16 + c);
                    float4 f1 = __ldg(((const float4*)esrc) + cv1.x * 16 + c);
                    float4 f2 = __ldg(((const float4*)esrc) + cv2.x * 16 + c);
                    float4 f3 = __ldg(((const float4*)esrc) + cv3.x * 16 + c);
                    float v0 = __int_as_float(cv0.y), v1 = __int_as_float(cv1.y);
                    float v2 = __int_as_float(cv2.y), v3 = __int_as_float(cv3.y);
                    xa.x += v0 * f0.x; xa.y += v0 * f0.y; xa.z += v0 * f0.z; xa.w += v0 * f0.w;
                    xb.x += v1 * f1.x; xb.y += v1 * f1.y; xb.z += v1 * f1.z; xb.w += v1 * f1.w;
                    xa.x += v2 * f2.x; xa.y += v2 * f2.y; xa.z += v2 * f2.z; xa.w += v2 * f2.w;
                    xb.x += v3 * f3.x; xb.y += v3 * f3.y; xb.z += v3 * f3.z; xb.w += v3 * f3.w;
                }
                for (; j < deg; j++) {
                    int2 cv0 = g_pad[start + j];
                    float v0 = __int_as_float(cv0.y);
                    float4 f0 = __ldg(((const float4*)esrc) + cv0.x * 16 + c);
                    xa.x += v0 * f0.x; xa.y += v0 * f0.y; xa.z += v0 * f0.z; xa.w += v0 * f0.w;
                }
                xa.x += xb.x; xa.y += xb.y; xa.z += xb.z; xa.w += xb.w;
                ev = __ldg(((const float4*)esrc) + node * 16 + c);
            }
            float4 u = make_float4(ev.x + xa.x, ev.y + xa.y, ev.z + xa.z, ev.w + xa.w);
            float4 v = make_float4(ev.x * xa.x, ev.y * xa.y, ev.z * xa.z, ev.w * xa.w);

            float uh0 = bfhi(u.x), uh1 = bfhi(u.y), uh2 = bfhi(u.z), uh3 = bfhi(u.w);
            float vh0 = bfhi(v.x), vh1 = bfhi(v.y), vh2 = bfhi(v.z), vh3 = bfhi(v.w);
            int offU = nd * KS + c * 8;          // k = 4c
            int offV = nd * KS + 128 + c * 8;    // k = 64 + 4c
            *(uint2*)(sm + AHI_OFF + offU) = make_uint2(packbf(uh0, uh1), packbf(uh2, uh3));
            *(uint2*)(sm + ALO_OFF + offU) = make_uint2(packbf(u.x - uh0, u.y - uh1),
                                                        packbf(u.z - uh2, u.w - uh3));
            *(uint2*)(sm + AHI_OFF + offV) = make_uint2(packbf(vh0, vh1), packbf(vh2, vh3));
            *(uint2*)(sm + ALO_OFF + offV) = make_uint2(packbf(v.x - vh0, v.y - vh1),
                                                        packbf(v.z - vh2, v.w - vh3));
        }
        __syncthreads();   // A tiles complete (also B on first iteration)

        // ---- tensor-core GEMM ----
        float acc[4][4];
        #pragma unroll
        for (int nt = 0; nt < 4; nt++)
            #pragma unroll
            for (int q = 0; q < 4; q++) acc[nt][q] = 0.f;

        #pragma unroll
        for (int ks = 0; ks < 8; ks++) {
            int kb = ks * 32 + lk;
            uint32_t ah0 = *(const uint32_t*)(smAh + rowA + kb);
            uint32_t ah1 = *(const uint32_t*)(smAh + rowA + 8 * KS + kb);
            uint32_t ah2 = *(const uint32_t*)(smAh + rowA + kb + 16);
            uint32_t ah3 = *(const uint32_t*)(smAh + rowA + 8 * KS + kb + 16);
            uint32_t al0 = *(const uint32_t*)(smAl + rowA + kb);
            uint32_t al1 = *(const uint32_t*)(smAl + rowA + 8 * KS + kb);
            uint32_t al2 = *(const uint32_t*)(smAl + rowA + kb + 16);
            uint32_t al3 = *(const uint32_t*)(smAl + rowA + 8 * KS + kb + 16);
            #pragma unroll
            for (int nt = 0; nt < 4; nt++) {
                int rowB = (wc * 32 + nt * 8 + (l >> 2)) * KS + kb;
                uint32_t bh0 = *(const uint32_t*)(smBh + rowB);
                uint32_t bh1 = *(const uint32_t*)(smBh + rowB + 16);
                uint32_t bl0 = *(const uint32_t*)(smBl + rowB);
                uint32_t bl1 = *(const uint32_t*)(smBl + rowB + 16);
                mma_bf16(acc[nt], ah0, ah1, ah2, ah3, bh0, bh1);
                mma_bf16(acc[nt], ah0, ah1, ah2, ah3, bl0, bl1);
                mma_bf16(acc[nt], al0, al1, al2, al3, bh0, bh1);
            }
        }

        // last layer: reset bucket heads for the next graph replay
        if (last && tid < 128) {
            int node = base + tid;
            if (node < N_NODES) g_head[node] = 0;
        }

        // ---- epilogue ----
        float ss0 = 0.f, ss1 = 0.f;
        #pragma unroll
        for (int nt = 0; nt < 4; nt++) {
            int col0 = wc * 32 + nt * 8 + (l & 3) * 2;
            float bc0 = bb[col0], bc1 = bb[col0 + 1];
            float h;
            h = acc[nt][0] + bc0; h = (h >= 0.f) ? h : NEG_SLOPE * h; acc[nt][0] = h; ss0 += h * h;
            h = acc[nt][1] + bc1; h = (h >= 0.f) ? h : NEG_SLOPE * h; acc[nt][1] = h; ss0 += h * h;
            h = acc[nt][2] + bc0; h = (h >= 0.f) ? h : NEG_SLOPE * h; acc[nt][2] = h; ss1 += h * h;
            h = acc[nt][3] + bc1; h = (h >= 0.f) ? h : NEG_SLOPE * h; acc[nt][3] = h; ss1 += h * h;
        }
        ss0 += __shfl_xor_sync(0xffffffffu, ss0, 1);
        ss0 += __shfl_xor_sync(0xffffffffu, ss0, 2);
        ss1 += __shfl_xor_sync(0xffffffffu, ss1, 1);
        ss1 += __shfl_xor_sync(0xffffffffu, ss1, 2);

        int r0l = 16 * wr + (l >> 2);
        if ((l & 3) == 0) {
            srow[r0l * 2 + wc] = ss0;
            srow[(r0l + 8) * 2 + wc] = ss1;
        }
        __syncthreads();   // srow ready; also guards A reuse next iteration
        float inv0 = rsqrtf(fmaxf(srow[r0l * 2] + srow[r0l * 2 + 1], 1e-24f));
        float inv1 = rsqrtf(fmaxf(srow[(r0l + 8) * 2] + srow[(r0l + 8) * 2 + 1], 1e-24f));

        int r0 = base + r0l;
        int r1 = r0 + 8;
        if (r0 < N_NODES) {
            #pragma unroll
            for (int nt = 0; nt < 4; nt++) {
                int col0 = wc * 32 + nt * 8 + (l & 3) * 2;
                float e0 = acc[nt][0] * inv0, e1 = acc[nt][1] * inv0;
                *(float2*)(edst + r0 * 64 + col0) = make_float2(e0, e1);
                red_add_v2(out + r0 * 64 + col0, 0.25f * e0, 0.25f * e1);
            }
        }
        if (r1 < N_NODES) {
            #pragma unroll
            for (int nt = 0; nt < 4; nt++) {
                int col0 = wc * 32 + nt * 8 + (l & 3) * 2;
                float e0 = acc[nt][2] * inv1, e1 = acc[nt][3] * inv1;
                *(float2*)(edst + r1 * 64 + col0) = make_float2(e0, e1);
                red_add_v2(out + r1 * 64 + col0, 0.25f * e0, 0.25f * e1);
            }
        }
        __syncthreads();   // srow reads done before next tile overwrites
    }
}

// ---------------------------------------------------------------------------
extern "C" void kernel_launch(void* const* d_in, const int* in_sizes, int n_in,
                              void* d_out, int out_size) {
    const int*   erow = (const int*)d_in[0];
    const int*   ecol = (const int*)d_in[1];
    const float* eval = (const float*)d_in[2];
    const float* ue   = (const float*)d_in[3];
    const float* ie   = (const float*)d_in[4];
    const float* W1   = (const float*)d_in[5];
    const float* b1   = (const float*)d_in[6];
    const float* W2   = (const float*)d_in[7];
    const float* b2   = (const float*)d_in[8];
    float* out = (float*)d_out;

    const int prelude_blocks = INIT_BLOCKS + SCAT_BLOCKS;   // 8750

    cudaFuncSetAttribute(k_layer_tc, cudaFuncAttributeMaxDynamicSharedMemorySize,
                         TC_SMEM);

    k_prelude<<<prelude_blocks, 256>>>(erow, ecol, eval, ue, ie, out);

    for (int l = 0; l < 3; l++) {
        k_layer_tc<<<PERSIST_BLOCKS, 512, TC_SMEM>>>(
            W1 + l * EMB * EMB, b1 + l * EMB,
            W2 + l * EMB * EMB, b2 + l * EMB, out, l & 1, l == 2);
    }
}